// round 1
// baseline (speedup 1.0000x reference)
#include <cuda_runtime.h>
#include <math.h>

#define NEGV (-9000000000000000.0f)

// ---------------- scratch (no allocations allowed) ----------------
__device__ float g_h[16 * 2048 * 64];     // 8.4 MB
__device__ float g_ssrc[16 * 2048];
__device__ float g_sdst[16 * 2048];

// ---------------- packed f32x2 helpers (sm_103a) ----------------
__device__ __forceinline__ unsigned long long pack2(float lo, float hi) {
    unsigned long long r;
    asm("mov.b64 %0, {%1, %2};" : "=l"(r) : "f"(lo), "f"(hi));
    return r;
}
__device__ __forceinline__ void unpack2(unsigned long long v, float& lo, float& hi) {
    asm("mov.b64 {%0, %1}, %2;" : "=f"(lo), "=f"(hi) : "l"(v));
}
__device__ __forceinline__ unsigned long long fma2(unsigned long long a,
                                                   unsigned long long b,
                                                   unsigned long long c) {
    unsigned long long d;
    asm("fma.rn.f32x2 %0, %1, %2, %3;" : "=l"(d) : "l"(a), "l"(b), "l"(c));
    return d;
}
__device__ __forceinline__ unsigned long long mul2(unsigned long long a,
                                                   unsigned long long b) {
    unsigned long long d;
    asm("mul.rn.f32x2 %0, %1, %2;" : "=l"(d) : "l"(a), "l"(b));
    return d;
}

// ================================================================
// Kernel A: h = x @ W  (+ s_src = h·a_src, s_dst = h·a_dst)
// block = 256 threads = 16 rows x 16 col-groups (4 cols each)
// ================================================================
__global__ void __launch_bounds__(256) gemm_h_kernel(const float* __restrict__ x,
                                                     const float* __restrict__ W,
                                                     const float* __restrict__ w2) {
    __shared__ float xs[16][256];
    const int t = threadIdx.x;
    const int rowg = t >> 4;   // 0..15
    const int cg   = t & 15;   // 0..15
    const long base_row = (long)blockIdx.x * 16;

    // cooperative load of 16 x-rows (16*256 floats) via float4
    {
        const float4* xg  = (const float4*)(x + base_row * 256);
        float4*       xs4 = (float4*)&xs[0][0];
        #pragma unroll
        for (int it = 0; it < 4; it++) xs4[t + it * 256] = xg[t + it * 256];
    }
    __syncthreads();

    float4 acc = make_float4(0.f, 0.f, 0.f, 0.f);
    const float* wp = W + cg * 4;
    #pragma unroll 8
    for (int k = 0; k < 256; k++) {
        const float  xv = xs[rowg][k];
        const float4 w4 = *(const float4*)(wp + k * 64);
        acc.x += xv * w4.x;
        acc.y += xv * w4.y;
        acc.z += xv * w4.z;
        acc.w += xv * w4.w;
    }

    const long grow = base_row + rowg;
    *(float4*)(g_h + grow * 64 + cg * 4) = acc;

    // s_src / s_dst partial dot products, reduce across the 16 lanes of a row
    const float4 as = *(const float4*)(w2 + cg * 4);
    const float4 ad = *(const float4*)(w2 + 64 + cg * 4);
    float ps = acc.x * as.x + acc.y * as.y + acc.z * as.z + acc.w * as.w;
    float pd = acc.x * ad.x + acc.y * ad.y + acc.z * ad.z + acc.w * ad.w;
    #pragma unroll
    for (int o = 1; o < 16; o <<= 1) {
        ps += __shfl_xor_sync(0xffffffffu, ps, o);
        pd += __shfl_xor_sync(0xffffffffu, pd, o);
    }
    if (cg == 0) {
        g_ssrc[grow] = ps;
        g_sdst[grow] = pd;
    }
}

// ================================================================
// Kernel B: flash-style masked softmax + P@V
// block = 256 threads, covers 64 i-rows of one batch.
// quad (4 threads) <-> one i-row; each quad-thread owns 16 out cols.
// j processed in 64-wide chunks with h-tile + p-tile in smem.
// ================================================================
__global__ void __launch_bounds__(256) attn_kernel(const int* __restrict__ adj,
                                                   float* __restrict__ out) {
    __shared__ float hs[64][64];     // h tile (j, c)
    __shared__ float psm[64][64];    // softmax numerators (r, j)
    __shared__ float sdst_sm[64];

    const int t  = threadIdx.x;
    const int b  = blockIdx.y;
    const int i0 = blockIdx.x * 64;
    const int r  = t >> 2;   // 0..63 : row within tile
    const int cg = t & 3;    // 0..3  : col group (16 cols)
    const int j0 = cg * 16;  // j sub-range this thread scores

    const long bn = (long)b * 2048;
    const float ssrc = g_ssrc[bn + i0 + r];
    const int* adj_row = adj + (bn + i0 + r) * 2048;

    unsigned long long acc[8];
    #pragma unroll
    for (int q = 0; q < 8; q++) acc[q] = 0ULL;
    float m = -INFINITY, l = 0.f;

    for (int jc = 0; jc < 2048; jc += 64) {
        __syncthreads();   // previous chunk's consumers done with hs/psm
        // ---- cooperative load h tile (64x64 f32) + s_dst chunk ----
        {
            const float4* hg = (const float4*)(g_h + (bn + jc) * 64);
            float4*       hd = (float4*)&hs[0][0];
            #pragma unroll
            for (int it = 0; it < 4; it++) hd[t + it * 256] = hg[t + it * 256];
            if (t < 64) sdst_sm[t] = g_sdst[bn + jc + t];
        }
        __syncthreads();

        // ---- score pass: this thread scores (r, j0..j0+15) ----
        float sc[16];
        float cmax = -INFINITY;
        const int4* a4p = (const int4*)(adj_row + jc + j0);
        #pragma unroll
        for (int q = 0; q < 4; q++) {
            const int4 a4 = a4p[q];
            const int aa0 = a4.x, aa1 = a4.y, aa2 = a4.z, aa3 = a4.w;
            float e0 = fmaxf(ssrc + sdst_sm[j0 + q * 4 + 0], 0.f);
            float e1 = fmaxf(ssrc + sdst_sm[j0 + q * 4 + 1], 0.f);
            float e2 = fmaxf(ssrc + sdst_sm[j0 + q * 4 + 2], 0.f);
            float e3 = fmaxf(ssrc + sdst_sm[j0 + q * 4 + 3], 0.f);
            sc[q * 4 + 0] = (aa0 > 0) ? e0 : NEGV;
            sc[q * 4 + 1] = (aa1 > 0) ? e1 : NEGV;
            sc[q * 4 + 2] = (aa2 > 0) ? e2 : NEGV;
            sc[q * 4 + 3] = (aa3 > 0) ? e3 : NEGV;
            cmax = fmaxf(cmax, fmaxf(fmaxf(sc[q * 4 + 0], sc[q * 4 + 1]),
                                     fmaxf(sc[q * 4 + 2], sc[q * 4 + 3])));
        }
        // quad max over the full 64-j chunk
        cmax = fmaxf(cmax, __shfl_xor_sync(0xffffffffu, cmax, 1));
        cmax = fmaxf(cmax, __shfl_xor_sync(0xffffffffu, cmax, 2));
        const float mnew = fmaxf(m, cmax);
        const float corr = __expf(m - mnew);   // m=-inf first chunk -> corr=0

        // exponentials + chunk l-sum
        float lsum = 0.f;
        #pragma unroll
        for (int i = 0; i < 16; i++) {
            const float p = __expf(sc[i] - mnew);
            sc[i] = p;
            lsum += p;
        }
        lsum += __shfl_xor_sync(0xffffffffu, lsum, 1);
        lsum += __shfl_xor_sync(0xffffffffu, lsum, 2);
        l = l * corr + lsum;
        m = mnew;

        // rescale accumulators (packed)
        const unsigned long long corr2 = pack2(corr, corr);
        #pragma unroll
        for (int q = 0; q < 8; q++) acc[q] = mul2(acc[q], corr2);

        // publish p for this row's quad
        #pragma unroll
        for (int q = 0; q < 4; q++) {
            *(float4*)&psm[r][j0 + q * 4] =
                make_float4(sc[q * 4 + 0], sc[q * 4 + 1], sc[q * 4 + 2], sc[q * 4 + 3]);
        }
        __syncwarp();   // quad-mates read each other's p

        // ---- FMA pass: acc[c] += p_j * h[j][c], 16 cols via 8x FFMA2 ----
        #pragma unroll 4
        for (int j = 0; j < 64; j++) {
            const float pv = psm[r][j];
            const unsigned long long p2 = pack2(pv, pv);
            const ulonglong2* hq = (const ulonglong2*)&hs[j][cg * 16];
            const ulonglong2 h0 = hq[0];
            const ulonglong2 h1 = hq[1];
            const ulonglong2 h2 = hq[2];
            const ulonglong2 h3 = hq[3];
            acc[0] = fma2(h0.x, p2, acc[0]);
            acc[1] = fma2(h0.y, p2, acc[1]);
            acc[2] = fma2(h1.x, p2, acc[2]);
            acc[3] = fma2(h1.y, p2, acc[3]);
            acc[4] = fma2(h2.x, p2, acc[4]);
            acc[5] = fma2(h2.y, p2, acc[5]);
            acc[6] = fma2(h3.x, p2, acc[6]);
            acc[7] = fma2(h3.y, p2, acc[7]);
        }
    }

    // ---- epilogue: divide by l, store 16 cols ----
    const float inv = 1.f / l;
    float o[16];
    #pragma unroll
    for (int q = 0; q < 8; q++) unpack2(acc[q], o[2 * q], o[2 * q + 1]);
    float* op = out + (bn + i0 + r) * 64 + cg * 16;
    #pragma unroll
    for (int q = 0; q < 4; q++) {
        *(float4*)(op + q * 4) = make_float4(o[q * 4 + 0] * inv, o[q * 4 + 1] * inv,
                                             o[q * 4 + 2] * inv, o[q * 4 + 3] * inv);
    }
}

// ================================================================
// launch
// inputs (metadata order): x f32[16,2048,256], adj i32[16,2048,2048],
//                          weight f32[256,64], weight2 f32[128,1]
// output: f32[16,2048,64]
// ================================================================
extern "C" void kernel_launch(void* const* d_in, const int* in_sizes, int n_in,
                              void* d_out, int out_size) {
    const float* x   = (const float*)d_in[0];
    const int*   adj = (const int*)d_in[1];
    const float* W   = (const float*)d_in[2];
    const float* w2  = (const float*)d_in[3];
    float* out = (float*)d_out;

    gemm_h_kernel<<<2048, 256>>>(x, W, w2);          // 32768 rows / 16 per block
    attn_kernel<<<dim3(32, 16), 256>>>(adj, out);    // 32 i-tiles x 16 batches
}

// round 3
// speedup vs baseline: 2.8029x; 2.8029x over previous
#include <cuda_runtime.h>
#include <math.h>

#define NEGV (-9000000000000000.0f)

// ---------------- scratch (no allocations allowed) ----------------
__device__ float g_h[16 * 2048 * 64];     // 8 MB
__device__ float g_ssrc[16 * 2048];
__device__ float g_sdst[16 * 2048];

typedef unsigned long long ull;

// ---------------- packed f32x2 helpers (sm_103a) ----------------
__device__ __forceinline__ ull pack2(float lo, float hi) {
    ull r;
    asm("mov.b64 %0, {%1, %2};" : "=l"(r) : "f"(lo), "f"(hi));
    return r;
}
__device__ __forceinline__ void unpack2(ull v, float& lo, float& hi) {
    asm("mov.b64 {%0, %1}, %2;" : "=f"(lo), "=f"(hi) : "l"(v));
}
__device__ __forceinline__ ull fma2(ull a, ull b, ull c) {
    ull d;
    asm("fma.rn.f32x2 %0, %1, %2, %3;" : "=l"(d) : "l"(a), "l"(b), "l"(c));
    return d;
}
__device__ __forceinline__ ull mul2(ull a, ull b) {
    ull d;
    asm("mul.rn.f32x2 %0, %1, %2;" : "=l"(d) : "l"(a), "l"(b));
    return d;
}
__device__ __forceinline__ ull add2(ull a, ull b) {
    ull d;
    asm("add.rn.f32x2 %0, %1, %2;" : "=l"(d) : "l"(a), "l"(b));
    return d;
}

// ================================================================
// Kernel A: h = x @ W  (+ s_src, s_dst)
// block = 256 threads, 64 rows. thread = (rowg 0..15 -> 4 rows,
// cg 0..15 -> 4 cols). W and x tiles cached in dynamic smem (128KB).
// ================================================================
__global__ void __launch_bounds__(256, 1) gemm_h_kernel(const float* __restrict__ x,
                                                        const float* __restrict__ W,
                                                        const float* __restrict__ w2) {
    extern __shared__ float dynsm[];
    float* ws = dynsm;            // [256][64]
    float* xs = dynsm + 16384;    // [64][256]

    const int t    = threadIdx.x;
    const int rowg = t >> 4;   // 0..15
    const int cg   = t & 15;   // 0..15
    const long base_row = (long)blockIdx.x * 64;

    // cooperative loads
    {
        const float4* wg  = (const float4*)W;
        float4*       ws4 = (float4*)ws;
        #pragma unroll
        for (int i = 0; i < 16; i++) ws4[t + i * 256] = wg[t + i * 256];
        const float4* xg  = (const float4*)(x + base_row * 256);
        float4*       xs4 = (float4*)xs;
        #pragma unroll
        for (int i = 0; i < 16; i++) xs4[t + i * 256] = xg[t + i * 256];
    }
    __syncthreads();

    ull acc2[4][2];
    #pragma unroll
    for (int r = 0; r < 4; r++) { acc2[r][0] = 0ULL; acc2[r][1] = 0ULL; }

    #pragma unroll 8
    for (int k = 0; k < 256; k++) {
        const ulonglong2 wv = *(const ulonglong2*)&ws[k * 64 + cg * 4];
        #pragma unroll
        for (int r = 0; r < 4; r++) {
            const float xv = xs[(rowg * 4 + r) * 256 + k];
            const ull x2 = pack2(xv, xv);
            acc2[r][0] = fma2(wv.x, x2, acc2[r][0]);
            acc2[r][1] = fma2(wv.y, x2, acc2[r][1]);
        }
    }

    // unpack, store h, compute s_src/s_dst partials
    const float4 as = *(const float4*)(w2 + cg * 4);
    const float4 ad = *(const float4*)(w2 + 64 + cg * 4);
    #pragma unroll
    for (int r = 0; r < 4; r++) {
        float a0, a1, a2, a3;
        unpack2(acc2[r][0], a0, a1);
        unpack2(acc2[r][1], a2, a3);
        const long grow = base_row + rowg * 4 + r;
        *(float4*)(g_h + grow * 64 + cg * 4) = make_float4(a0, a1, a2, a3);

        float ps = a0 * as.x + a1 * as.y + a2 * as.z + a3 * as.w;
        float pd = a0 * ad.x + a1 * ad.y + a2 * ad.z + a3 * ad.w;
        #pragma unroll
        for (int o = 1; o < 16; o <<= 1) {
            ps += __shfl_xor_sync(0xffffffffu, ps, o);
            pd += __shfl_xor_sync(0xffffffffu, pd, o);
        }
        if (cg == 0) {
            g_ssrc[grow] = ps;
            g_sdst[grow] = pd;
        }
    }
}

// ================================================================
// Kernel B: flash-style masked softmax + P@V, register-blocked.
// block = 256 threads, 64 i-rows of one batch.
// thread (rg=t>>4: 4 rows, cg=(t>>2)&3: 16 cols, jg=t&3: 16 j's).
// p kept in registers; h tile in swizzled smem read once per 4-row
// group; accumulators reduced over jg at the end via shfl.
// NOTE: scores are replicated across the 4 cg lanes of each (rg,jg),
// so softmax reductions must run over jg bits (0..1) ONLY — summing
// over cg bits too would 4x-overcount l (the Round-2 bug).
// ================================================================
__global__ void __launch_bounds__(256, 1) attn_kernel(const int* __restrict__ adj,
                                                      float* __restrict__ out) {
    __shared__ float hs[64 * 64];     // swizzled h tile
    __shared__ float sdst_sm[64];

    const int t  = threadIdx.x;
    const int jg = t & 3;
    const int cg = (t >> 2) & 3;
    const int rg = t >> 4;            // 0..15
    const int b  = blockIdx.y;
    const int i0 = blockIdx.x * 64;

    const long bn = (long)b * 2048;
    const long r0 = bn + i0 + rg * 4;

    float ssrc[4];
    #pragma unroll
    for (int k = 0; k < 4; k++) ssrc[k] = g_ssrc[r0 + k];
    const int* adjp = adj + r0 * 2048;

    ull acc[4][8];
    #pragma unroll
    for (int k = 0; k < 4; k++)
        #pragma unroll
        for (int q = 0; q < 8; q++) acc[k][q] = 0ULL;
    float m[4] = {-INFINITY, -INFINITY, -INFINITY, -INFINITY};
    float l[4] = {0.f, 0.f, 0.f, 0.f};

    for (int jc = 0; jc < 2048; jc += 64) {
        __syncthreads();
        // ---- cooperative swizzled load of h tile ----
        {
            const float4* hg = (const float4*)(g_h + (bn + jc) * 64);
            #pragma unroll
            for (int it = 0; it < 4; it++) {
                const int f  = t + it * 256;     // float4 index
                const int j  = f >> 4;
                const int g0 = f & 15;
                const int ph = (g0 + j + (j >> 4)) & 15;
                *(float4*)&hs[j * 64 + ph * 4] = hg[f];
            }
            if (t < 64) sdst_sm[t] = g_sdst[bn + jc + t];
        }
        __syncthreads();

        // ---- scores for 4 rows x my 16 j's (j = jg*16 + s) ----
        float sd[16];
        #pragma unroll
        for (int q = 0; q < 4; q++)
            *(float4*)&sd[q * 4] = *(const float4*)&sdst_sm[jg * 16 + q * 4];

        float p[4][16];
        float rmax[4];
        #pragma unroll
        for (int k = 0; k < 4; k++) {
            const int4* a4 = (const int4*)(adjp + (long)k * 2048 + jc + jg * 16);
            float mx = -INFINITY;
            #pragma unroll
            for (int q = 0; q < 4; q++) {
                const int4 a = a4[q];
                const float e0 = fmaxf(ssrc[k] + sd[q * 4 + 0], 0.f);
                const float e1 = fmaxf(ssrc[k] + sd[q * 4 + 1], 0.f);
                const float e2 = fmaxf(ssrc[k] + sd[q * 4 + 2], 0.f);
                const float e3 = fmaxf(ssrc[k] + sd[q * 4 + 3], 0.f);
                p[k][q * 4 + 0] = (a.x > 0) ? e0 : NEGV;
                p[k][q * 4 + 1] = (a.y > 0) ? e1 : NEGV;
                p[k][q * 4 + 2] = (a.z > 0) ? e2 : NEGV;
                p[k][q * 4 + 3] = (a.w > 0) ? e3 : NEGV;
                mx = fmaxf(mx, fmaxf(fmaxf(p[k][q * 4 + 0], p[k][q * 4 + 1]),
                                     fmaxf(p[k][q * 4 + 2], p[k][q * 4 + 3])));
            }
            rmax[k] = mx;
        }
        // row max over the 4 jg lanes (bits 0..1); cg lanes are duplicates
        #pragma unroll
        for (int o = 1; o < 4; o <<= 1) {
            #pragma unroll
            for (int k = 0; k < 4; k++)
                rmax[k] = fmaxf(rmax[k], __shfl_xor_sync(0xffffffffu, rmax[k], o));
        }

        float corr[4];
        #pragma unroll
        for (int k = 0; k < 4; k++) {
            const float mn = fmaxf(m[k], rmax[k]);
            corr[k] = __expf(m[k] - mn);
            m[k] = mn;
        }

        float ls[4];
        #pragma unroll
        for (int k = 0; k < 4; k++) {
            float s = 0.f;
            #pragma unroll
            for (int q = 0; q < 16; q++) {
                const float pv = __expf(p[k][q] - m[k]);
                p[k][q] = pv;
                s += pv;
            }
            ls[k] = s;
        }
        // sum over jg bits ONLY (jg slices partition the chunk; cg duplicates)
        #pragma unroll
        for (int o = 1; o < 4; o <<= 1) {
            #pragma unroll
            for (int k = 0; k < 4; k++)
                ls[k] += __shfl_xor_sync(0xffffffffu, ls[k], o);
        }
        #pragma unroll
        for (int k = 0; k < 4; k++) l[k] = l[k] * corr[k] + ls[k];

        // rescale accumulators
        #pragma unroll
        for (int k = 0; k < 4; k++) {
            const ull c2 = pack2(corr[k], corr[k]);
            #pragma unroll
            for (int q = 0; q < 8; q++) acc[k][q] = mul2(acc[k][q], c2);
        }

        // ---- FMA over my 16 j's: acc[k][cols] += p[k][j] * h[j][cols] ----
        #pragma unroll
        for (int s = 0; s < 16; s++) {
            const int j   = jg * 16 + s;
            const int rot = s + jg;          // = (j&15) + (j>>4)
            ull hv[8];
            #pragma unroll
            for (int kk = 0; kk < 4; kk++) {
                const int ph = ((cg * 4 + kk) + rot) & 15;
                const ulonglong2 v = *(const ulonglong2*)&hs[j * 64 + ph * 4];
                hv[kk * 2 + 0] = v.x;
                hv[kk * 2 + 1] = v.y;
            }
            #pragma unroll
            for (int k = 0; k < 4; k++) {
                const ull p2 = pack2(p[k][s], p[k][s]);
                #pragma unroll
                for (int q = 0; q < 8; q++) acc[k][q] = fma2(hv[q], p2, acc[k][q]);
            }
        }
    }

    // ---- reduce partial accumulators over jg (lane bits 0..1) ----
    #pragma unroll
    for (int o = 1; o < 4; o <<= 1) {
        #pragma unroll
        for (int k = 0; k < 4; k++)
            #pragma unroll
            for (int q = 0; q < 8; q++) {
                const ull other = __shfl_xor_sync(0xffffffffu, acc[k][q], o);
                acc[k][q] = add2(acc[k][q], other);
            }
    }

    // ---- epilogue: one jg lane per (row-group, col-group) stores ----
    if (jg == 0) {
        #pragma unroll
        for (int k = 0; k < 4; k++) {
            const float inv = 1.f / l[k];
            float o8[16];
            #pragma unroll
            for (int q = 0; q < 8; q++) unpack2(acc[k][q], o8[2 * q], o8[2 * q + 1]);
            float* op = out + (r0 + k) * 64 + cg * 16;
            #pragma unroll
            for (int q = 0; q < 4; q++) {
                *(float4*)(op + q * 4) =
                    make_float4(o8[q * 4 + 0] * inv, o8[q * 4 + 1] * inv,
                                o8[q * 4 + 2] * inv, o8[q * 4 + 3] * inv);
            }
        }
    }
}

// ================================================================
// launch
// inputs: x f32[16,2048,256], adj i32[16,2048,2048],
//         weight f32[256,64], weight2 f32[128,1]
// output: f32[16,2048,64]
// ================================================================
extern "C" void kernel_launch(void* const* d_in, const int* in_sizes, int n_in,
                              void* d_out, int out_size) {
    const float* x   = (const float*)d_in[0];
    const int*   adj = (const int*)d_in[1];
    const float* W   = (const float*)d_in[2];
    const float* w2  = (const float*)d_in[3];
    float* out = (float*)d_out;

    cudaFuncSetAttribute(gemm_h_kernel,
                         cudaFuncAttributeMaxDynamicSharedMemorySize, 131072);

    gemm_h_kernel<<<512, 256, 131072>>>(x, W, w2);   // 64 rows per block
    attn_kernel<<<dim3(32, 16), 256>>>(adj, out);    // 32 i-tiles x 16 batches
}